// round 8
// baseline (speedup 1.0000x reference)
#include <cuda_runtime.h>
#include <cuda_bf16.h>
#include <math.h>

#define NN 50000
#define NE 800000
#define NEL 850000
#define DF 128
#define DLIN 512
#define DOUT 4
#define NBLK 49   // ceil(NN/1024)

// ---------------- device scratch ----------------
__device__ __align__(16) float g_x[NN * DF];
__device__ __align__(16) float g_h[NN * DF];
__device__ __align__(16) float g_es[NN];
__device__ __align__(16) float g_ed[NN];
__device__ __align__(16) int g_src[NEL];
__device__ __align__(16) int g_dst[NEL];
__device__ __align__(16) float g_y0[NN * DLIN];
__device__ __align__(16) float g_y1[NN * DLIN];
// CSR
__device__ __align__(16) int g_deg[NN];
__device__ __align__(16) int g_incl[NN];
__device__ __align__(16) int g_bsum[NBLK];
__device__ __align__(16) int g_boff[NBLK];
__device__ __align__(16) int g_rowstart[NN + 1];
__device__ __align__(16) int g_cursor[NN];
__device__ __align__(16) int g_csr[NEL];
__device__ int g_is64;

// ---------------- helpers ----------------
__device__ __forceinline__ float leaky(float v) { return v > 0.f ? v : 0.2f * v; }
__device__ __forceinline__ float to_tf32(float f) {
    float r;
    asm("cvt.rna.tf32.f32 %0, %1;" : "=f"(r) : "f"(f));
    return r;
}
__device__ __forceinline__ float2 split_tf32(float v) {
    float h = to_tf32(v);
    return make_float2(h, to_tf32(v - h));
}

// ---------------- edge dtype probe ----------------
__global__ void k_detect_dtype(const int* __restrict__ ei32) {
    if (threadIdx.x != 0 || blockIdx.x != 0) return;
    int zeros = 0;
    for (int i = 0; i < 256; i++)
        if (ei32[2 * i + 1] == 0) zeros++;
    g_is64 = (zeros >= 250) ? 1 : 0;
}

__global__ void k_build_edges(const void* __restrict__ ei) {
    int i = blockIdx.x * blockDim.x + threadIdx.x;
    if (i >= NEL) return;
    int s, d;
    if (i < NE) {
        if (g_is64) {
            const long long* p = (const long long*)ei;
            s = (int)p[i];
            d = (int)p[NE + i];
        } else {
            const int* p = (const int*)ei;
            s = p[i];
            d = p[NE + i];
        }
        s = min(max(s, 0), NN - 1);
        d = min(max(d, 0), NN - 1);
    } else {
        s = i - NE;
        d = i - NE;
    }
    g_src[i] = s;
    g_dst[i] = d;
}

// ---------------- CSR build ----------------
__global__ void k_zero_deg() {
    int i = blockIdx.x * blockDim.x + threadIdx.x;
    if (i < NN) g_deg[i] = 0;
}
__global__ void k_hist() {
    int e = blockIdx.x * blockDim.x + threadIdx.x;
    if (e >= NEL) return;
    atomicAdd(&g_deg[g_dst[e]], 1);
}
__global__ void k_scan1() {
    __shared__ int sm[1024];
    int i = blockIdx.x * 1024 + threadIdx.x;
    int v = (i < NN) ? g_deg[i] : 0;
    sm[threadIdx.x] = v;
    __syncthreads();
    for (int off = 1; off < 1024; off <<= 1) {
        int t = (threadIdx.x >= off) ? sm[threadIdx.x - off] : 0;
        __syncthreads();
        sm[threadIdx.x] += t;
        __syncthreads();
    }
    if (i < NN) g_incl[i] = sm[threadIdx.x];
    if (threadIdx.x == 1023) g_bsum[blockIdx.x] = sm[1023];
}
__global__ void k_scan2() {
    if (threadIdx.x == 0 && blockIdx.x == 0) {
        int run = 0;
        for (int b = 0; b < NBLK; b++) {
            int t = g_bsum[b];
            g_boff[b] = run;
            run += t;
        }
    }
}
__global__ void k_scan3() {
    int i = blockIdx.x * blockDim.x + threadIdx.x;
    if (i < NN) {
        int rs = g_incl[i] - g_deg[i] + g_boff[i >> 10];
        g_rowstart[i] = rs;
        g_cursor[i] = rs;
    }
    if (i == 0) g_rowstart[NN] = NEL;
}
__global__ void k_scatter() {
    int e = blockIdx.x * blockDim.x + threadIdx.x;
    if (e >= NEL) return;
    int pos = atomicAdd(&g_cursor[g_dst[e]], 1);
    g_csr[pos] = g_src[e];
}

// ---------------- split-TF32 tensor-core GEMM, hi/lo precomputed in smem ----------------
#define ASP_STRIDE 36
#define BSP_STRIDE 136
#define SMEM_MMA (128 * ASP_STRIDE * 8 + 32 * BSP_STRIDE * 8)

#define MMA_TF32(ACC, A0, A1, A2, A3, B0, B1)                                   \
    asm volatile(                                                                \
        "mma.sync.aligned.m16n8k8.row.col.f32.tf32.tf32.f32 "                    \
        "{%0,%1,%2,%3}, {%4,%5,%6,%7}, {%8,%9}, {%0,%1,%2,%3};"                  \
        : "+f"((ACC)[0]), "+f"((ACC)[1]), "+f"((ACC)[2]), "+f"((ACC)[3])         \
        : "r"(__float_as_uint(A0)), "r"(__float_as_uint(A1)),                    \
          "r"(__float_as_uint(A2)), "r"(__float_as_uint(A3)),                    \
          "r"(__float_as_uint(B0)), "r"(__float_as_uint(B1)))

__global__ __launch_bounds__(256, 2) void k_mma(
    const float* __restrict__ A, const float* __restrict__ B,
    const float* __restrict__ bias, float* __restrict__ C,
    int M, int N, int K, int act) {
    extern __shared__ char smem_buf[];
    float2 (*AsP)[ASP_STRIDE] = (float2(*)[ASP_STRIDE])smem_buf;                     // [m][k] (hi,lo)
    float2 (*BsP)[BSP_STRIDE] = (float2(*)[BSP_STRIDE])(smem_buf + 128 * ASP_STRIDE * 8); // [k][n]

    const int tid = threadIdx.x;
    const int wid = tid >> 5;
    const int lane = tid & 31;
    const int warpM = wid >> 2;
    const int warpN = wid & 3;
    const int rowBase = blockIdx.y * 128;
    const int colBase = blockIdx.x * 128;

    const int lq = lane >> 2;
    const int lr = lane & 3;

    float acc[4][4][4];
#pragma unroll
    for (int i = 0; i < 4; i++)
#pragma unroll
        for (int j = 0; j < 4; j++)
#pragma unroll
            for (int r = 0; r < 4; r++) acc[i][j][r] = 0.f;

    const int aRow0 = tid >> 3;
    const int aCol4 = (tid & 7) << 2;
    const int bRow0 = tid >> 5;
    const int bCol4 = (tid & 31) << 2;

    for (int k0 = 0; k0 < K; k0 += 32) {
#pragma unroll
        for (int i = 0; i < 4; i++) {
            int r = aRow0 + i * 32;
            int gr = rowBase + r;
            if (gr >= M) gr = M - 1;
            float4 v = *(const float4*)(A + (size_t)gr * K + k0 + aCol4);
            AsP[r][aCol4 + 0] = split_tf32(v.x);
            AsP[r][aCol4 + 1] = split_tf32(v.y);
            AsP[r][aCol4 + 2] = split_tf32(v.z);
            AsP[r][aCol4 + 3] = split_tf32(v.w);
        }
#pragma unroll
        for (int i = 0; i < 4; i++) {
            int r = bRow0 + i * 8;
            float4 v = *(const float4*)(B + (size_t)(k0 + r) * N + colBase + bCol4);
            BsP[r][bCol4 + 0] = split_tf32(v.x);
            BsP[r][bCol4 + 1] = split_tf32(v.y);
            BsP[r][bCol4 + 2] = split_tf32(v.z);
            BsP[r][bCol4 + 3] = split_tf32(v.w);
        }
        __syncthreads();

#pragma unroll
        for (int kk = 0; kk < 4; kk++) {
            const int kb = kk * 8;
            float2 bf[4][2];
#pragma unroll
            for (int nt = 0; nt < 4; nt++) {
                int c = warpN * 32 + nt * 8 + lq;
                bf[nt][0] = BsP[kb + lr][c];
                bf[nt][1] = BsP[kb + lr + 4][c];
            }
#pragma unroll
            for (int mt = 0; mt < 4; mt++) {
                int r = warpM * 64 + mt * 16 + lq;
                float2 a0 = AsP[r][kb + lr];
                float2 a1 = AsP[r + 8][kb + lr];
                float2 a2 = AsP[r][kb + lr + 4];
                float2 a3 = AsP[r + 8][kb + lr + 4];
#pragma unroll
                for (int nt = 0; nt < 4; nt++) {
                    MMA_TF32(acc[mt][nt], a0.y, a1.y, a2.y, a3.y, bf[nt][0].x, bf[nt][1].x); // lo*hi
                    MMA_TF32(acc[mt][nt], a0.x, a1.x, a2.x, a3.x, bf[nt][0].y, bf[nt][1].y); // hi*lo
                    MMA_TF32(acc[mt][nt], a0.x, a1.x, a2.x, a3.x, bf[nt][0].x, bf[nt][1].x); // hi*hi
                }
            }
        }
        __syncthreads();
    }

#pragma unroll
    for (int mt = 0; mt < 4; mt++) {
        int r0 = rowBase + warpM * 64 + mt * 16 + lq;
#pragma unroll
        for (int nt = 0; nt < 4; nt++) {
            int c = colBase + warpN * 32 + nt * 8 + lr * 2;
            float b0 = bias ? bias[c] : 0.f;
            float b1 = bias ? bias[c + 1] : 0.f;
            if (r0 < M) {
                float v0 = acc[mt][nt][0] + b0;
                float v1 = acc[mt][nt][1] + b1;
                if (act) { v0 = fmaxf(v0, 0.f); v1 = fmaxf(v1, 0.f); }
                *(float2*)(C + (size_t)r0 * N + c) = make_float2(v0, v1);
            }
            if (r0 + 8 < M) {
                float v2 = acc[mt][nt][2] + b0;
                float v3 = acc[mt][nt][3] + b1;
                if (act) { v2 = fmaxf(v2, 0.f); v3 = fmaxf(v3, 0.f); }
                *(float2*)(C + (size_t)(r0 + 8) * N + c) = make_float2(v2, v3);
            }
        }
    }
}

// ---------------- per-node attention scalars ----------------
__global__ void k_es_ed(const float* __restrict__ a_src, const float* __restrict__ a_dst) {
    int n = blockIdx.x * (blockDim.x >> 5) + (threadIdx.x >> 5);
    int lane = threadIdx.x & 31;
    if (n >= NN) return;
    float4 hv = *(const float4*)(g_h + (size_t)n * DF + lane * 4);
    float4 as = *(const float4*)(a_src + lane * 4);
    float4 ad = *(const float4*)(a_dst + lane * 4);
    float s = hv.x * as.x + hv.y * as.y + hv.z * as.z + hv.w * as.w;
    float d = hv.x * ad.x + hv.y * ad.y + hv.z * ad.z + hv.w * ad.w;
#pragma unroll
    for (int o = 16; o > 0; o >>= 1) {
        s += __shfl_xor_sync(0xffffffff, s, o);
        d += __shfl_xor_sync(0xffffffff, d, o);
    }
    if (lane == 0) {
        g_es[n] = s;
        g_ed[n] = d;
    }
}

// ---------------- fused per-node softmax + aggregation (warp per node) ----------------
__global__ void k_node_aggr(const float* __restrict__ bias) {
    int n = blockIdx.x * (blockDim.x >> 5) + (threadIdx.x >> 5);
    int lane = threadIdx.x & 31;
    if (n >= NN) return;
    int r0 = g_rowstart[n];
    int r1 = g_rowstart[n + 1];
    float edn = g_ed[n];

    float m = -1e30f;
    for (int i = r0 + lane; i < r1; i += 32)
        m = fmaxf(m, leaky(g_es[g_csr[i]] + edn));
#pragma unroll
    for (int o = 16; o > 0; o >>= 1)
        m = fmaxf(m, __shfl_xor_sync(0xffffffff, m, o));

    float s = 0.f;
    for (int i = r0 + lane; i < r1; i += 32)
        s += expf(leaky(g_es[g_csr[i]] + edn) - m);
#pragma unroll
    for (int o = 16; o > 0; o >>= 1)
        s += __shfl_xor_sync(0xffffffff, s, o);
    float inv = 1.f / s;

    float4 acc = make_float4(0.f, 0.f, 0.f, 0.f);
    for (int i = r0; i < r1; i++) {
        int src = g_csr[i];
        float w = expf(leaky(g_es[src] + edn) - m) * inv;
        float4 hv = *(const float4*)(g_h + (size_t)src * DF + lane * 4);
        acc.x += w * hv.x;
        acc.y += w * hv.y;
        acc.z += w * hv.z;
        acc.w += w * hv.w;
    }
    float4 bv = *(const float4*)(bias + lane * 4);
    float4 r;
    r.x = leaky(acc.x + bv.x);
    r.y = leaky(acc.y + bv.y);
    r.z = leaky(acc.z + bv.z);
    r.w = leaky(acc.w + bv.w);
    *(float4*)(g_x + (size_t)n * DF + lane * 4) = r;
}

// ---------------- output head ----------------
__global__ void k_out(const float* __restrict__ Y, const float* __restrict__ Wout,
                      const float* __restrict__ bout, float* __restrict__ out) {
    int n = blockIdx.x * (blockDim.x >> 5) + (threadIdx.x >> 5);
    int lane = threadIdx.x & 31;
    if (n >= NN) return;
    float acc0 = 0.f, acc1 = 0.f, acc2 = 0.f, acc3 = 0.f;
    const float* y = Y + (size_t)n * DLIN;
    for (int k = lane; k < DLIN; k += 32) {
        float v = y[k];
        const float4 wv = *(const float4*)(Wout + k * 4);
        acc0 += v * wv.x;
        acc1 += v * wv.y;
        acc2 += v * wv.z;
        acc3 += v * wv.w;
    }
#pragma unroll
    for (int o = 16; o > 0; o >>= 1) {
        acc0 += __shfl_xor_sync(0xffffffff, acc0, o);
        acc1 += __shfl_xor_sync(0xffffffff, acc1, o);
        acc2 += __shfl_xor_sync(0xffffffff, acc2, o);
        acc3 += __shfl_xor_sync(0xffffffff, acc3, o);
    }
    if (lane == 0) {
        float4 r;
        r.x = acc0 + bout[0];
        r.y = acc1 + bout[1];
        r.z = acc2 + bout[2];
        r.w = acc3 + bout[3];
        *(float4*)(out + (size_t)n * 4) = r;
    }
}

extern "C" void kernel_launch(void* const* d_in, const int* in_sizes, int n_in,
                              void* d_out, int out_size) {
    const float *x, *conv_W, *conv_as, *conv_ad, *conv_b;
    const float *lin_W0, *lin_b0, *lin_W1, *lin_b1, *lin_W2, *lin_b2, *lin_Wout, *lin_bout;
    const void* ei;

    if (in_sizes[0] == NN * DF) {
        x        = (const float*)d_in[0];
        ei       = d_in[1];
        conv_W   = (const float*)d_in[2];
        conv_as  = (const float*)d_in[3];
        conv_ad  = (const float*)d_in[4];
        conv_b   = (const float*)d_in[5];
        lin_W0   = (const float*)d_in[6];
        lin_b0   = (const float*)d_in[7];
        lin_W1   = (const float*)d_in[8];
        lin_b1   = (const float*)d_in[9];
        lin_W2   = (const float*)d_in[10];
        lin_b2   = (const float*)d_in[11];
        lin_Wout = (const float*)d_in[12];
        lin_bout = (const float*)d_in[13];
    } else {
        conv_W   = (const float*)d_in[0];
        conv_ad  = (const float*)d_in[1];
        conv_as  = (const float*)d_in[2];
        conv_b   = (const float*)d_in[3];
        ei       = d_in[4];
        lin_W0   = (const float*)d_in[5];
        lin_W1   = (const float*)d_in[6];
        lin_W2   = (const float*)d_in[7];
        lin_Wout = (const float*)d_in[8];
        lin_b0   = (const float*)d_in[9];
        lin_b1   = (const float*)d_in[10];
        lin_b2   = (const float*)d_in[11];
        lin_bout = (const float*)d_in[12];
        x        = (const float*)d_in[13];
    }
    float* out = (float*)d_out;

    void *p_x, *p_h, *p_y0, *p_y1;
    cudaGetSymbolAddress(&p_x, g_x);
    cudaGetSymbolAddress(&p_h, g_h);
    cudaGetSymbolAddress(&p_y0, g_y0);
    cudaGetSymbolAddress(&p_y1, g_y1);

    static int smem_set = 0;
    if (!smem_set) {
        cudaFuncSetAttribute(k_mma, cudaFuncAttributeMaxDynamicSharedMemorySize, SMEM_MMA);
        smem_set = 1;
    }

    // edges + CSR (once per launch)
    k_detect_dtype<<<1, 32>>>((const int*)ei);
    k_build_edges<<<(NEL + 255) / 256, 256>>>(ei);
    k_zero_deg<<<(NN + 255) / 256, 256>>>();
    k_hist<<<(NEL + 255) / 256, 256>>>();
    k_scan1<<<NBLK, 1024>>>();
    k_scan2<<<1, 32>>>();
    k_scan3<<<(NN + 255) / 256, 256>>>();
    k_scatter<<<(NEL + 255) / 256, 256>>>();

    dim3 grid128(1, (NN + 127) / 128);
    dim3 grid512(DLIN / 128, (NN + 127) / 128);
    const int wpb = 8;
    const int nodeBlocks = (NN + wpb - 1) / wpb;

    const float* curX = x;
    for (int layer = 0; layer < 3; layer++) {
        const float* W  = conv_W + (size_t)layer * DF * DF;
        const float* as = conv_as + (size_t)layer * DF;
        const float* ad = conv_ad + (size_t)layer * DF;
        const float* b  = conv_b + (size_t)layer * DF;

        k_mma<<<grid128, 256, SMEM_MMA>>>(curX, W, nullptr, (float*)p_h, NN, DF, DF, 0);
        k_es_ed<<<nodeBlocks, wpb * 32>>>(as, ad);
        k_node_aggr<<<nodeBlocks, wpb * 32>>>(b);
        curX = (const float*)p_x;
    }

    k_mma<<<grid512, 256, SMEM_MMA>>>((const float*)p_x, lin_W0, lin_b0, (float*)p_y0, NN, DLIN, DF, 1);
    k_mma<<<grid512, 256, SMEM_MMA>>>((const float*)p_y0, lin_W1, lin_b1, (float*)p_y1, NN, DLIN, DLIN, 1);
    k_mma<<<grid512, 256, SMEM_MMA>>>((const float*)p_y1, lin_W2, lin_b2, (float*)p_y0, NN, DLIN, DLIN, 1);
    k_out<<<nodeBlocks, wpb * 32>>>((const float*)p_y0, lin_Wout, lin_bout, out);
}

// round 10
// speedup vs baseline: 1.8858x; 1.8858x over previous
#include <cuda_runtime.h>
#include <cuda_bf16.h>
#include <math.h>

#define NN 50000
#define NE 800000
#define NEL 850000
#define DF 128
#define DLIN 512
#define DOUT 4
#define NBLK 49   // ceil(NN/1024)

// ---------------- device scratch ----------------
__device__ __align__(16) float g_x[NN * DF];
__device__ __align__(16) float g_h[NN * DF];
__device__ __align__(16) float g_es[NN];
__device__ __align__(16) float g_ed[NN];
__device__ __align__(16) int g_src[NEL];
__device__ __align__(16) int g_dst[NEL];
__device__ __align__(16) float g_y0[NN * DLIN];
__device__ __align__(16) float g_y1[NN * DLIN];
// CSR
__device__ __align__(16) int g_deg[NN];
__device__ __align__(16) int g_incl[NN];
__device__ __align__(16) int g_bsum[NBLK];
__device__ __align__(16) int g_boff[NBLK];
__device__ __align__(16) int g_rowstart[NN + 1];
__device__ __align__(16) int g_cursor[NN];
__device__ __align__(16) int g_csr[NEL];
__device__ int g_is64;

// ---------------- helpers ----------------
__device__ __forceinline__ float leaky(float v) { return v > 0.f ? v : 0.2f * v; }
__device__ __forceinline__ float to_tf32(float f) {
    float r;
    asm("cvt.rna.tf32.f32 %0, %1;" : "=f"(r) : "f"(f));
    return r;
}

// ---------------- edge dtype probe ----------------
__global__ void k_detect_dtype(const int* __restrict__ ei32) {
    if (threadIdx.x != 0 || blockIdx.x != 0) return;
    int zeros = 0;
    for (int i = 0; i < 256; i++)
        if (ei32[2 * i + 1] == 0) zeros++;
    g_is64 = (zeros >= 250) ? 1 : 0;
}

__global__ void k_build_edges(const void* __restrict__ ei) {
    int i = blockIdx.x * blockDim.x + threadIdx.x;
    if (i >= NEL) return;
    int s, d;
    if (i < NE) {
        if (g_is64) {
            const long long* p = (const long long*)ei;
            s = (int)p[i];
            d = (int)p[NE + i];
        } else {
            const int* p = (const int*)ei;
            s = p[i];
            d = p[NE + i];
        }
        s = min(max(s, 0), NN - 1);
        d = min(max(d, 0), NN - 1);
    } else {
        s = i - NE;
        d = i - NE;
    }
    g_src[i] = s;
    g_dst[i] = d;
}

// ---------------- CSR build ----------------
__global__ void k_zero_deg() {
    int i = blockIdx.x * blockDim.x + threadIdx.x;
    if (i < NN) g_deg[i] = 0;
}
__global__ void k_hist() {
    int e = blockIdx.x * blockDim.x + threadIdx.x;
    if (e >= NEL) return;
    atomicAdd(&g_deg[g_dst[e]], 1);
}
__global__ void k_scan1() {
    __shared__ int sm[1024];
    int i = blockIdx.x * 1024 + threadIdx.x;
    int v = (i < NN) ? g_deg[i] : 0;
    sm[threadIdx.x] = v;
    __syncthreads();
    for (int off = 1; off < 1024; off <<= 1) {
        int t = (threadIdx.x >= off) ? sm[threadIdx.x - off] : 0;
        __syncthreads();
        sm[threadIdx.x] += t;
        __syncthreads();
    }
    if (i < NN) g_incl[i] = sm[threadIdx.x];
    if (threadIdx.x == 1023) g_bsum[blockIdx.x] = sm[1023];
}
__global__ void k_scan2() {
    if (threadIdx.x == 0 && blockIdx.x == 0) {
        int run = 0;
        for (int b = 0; b < NBLK; b++) {
            int t = g_bsum[b];
            g_boff[b] = run;
            run += t;
        }
    }
}
__global__ void k_scan3() {
    int i = blockIdx.x * blockDim.x + threadIdx.x;
    if (i < NN) {
        int rs = g_incl[i] - g_deg[i] + g_boff[i >> 10];
        g_rowstart[i] = rs;
        g_cursor[i] = rs;
    }
    if (i == 0) g_rowstart[NN] = NEL;
}
__global__ void k_scatter() {
    int e = blockIdx.x * blockDim.x + threadIdx.x;
    if (e >= NEL) return;
    int pos = atomicAdd(&g_cursor[g_dst[e]], 1);
    g_csr[pos] = g_src[e];
}

// ---------------- split-TF32 tensor-core GEMM, SoA hi/lo in smem ----------------
// Strides identical to the proven R7 layout (32-bit LDS, conflict-free).
#define AS_STRIDE 36
#define BS_STRIDE 136
#define AS_ELEMS (128 * AS_STRIDE)
#define BS_ELEMS (32 * BS_STRIDE)
#define SMEM_MMA ((2 * AS_ELEMS + 2 * BS_ELEMS) * 4)

#define MMA_TF32(ACC, A0, A1, A2, A3, B0, B1)                                   \
    asm volatile(                                                                \
        "mma.sync.aligned.m16n8k8.row.col.f32.tf32.tf32.f32 "                    \
        "{%0,%1,%2,%3}, {%4,%5,%6,%7}, {%8,%9}, {%0,%1,%2,%3};"                  \
        : "+f"((ACC)[0]), "+f"((ACC)[1]), "+f"((ACC)[2]), "+f"((ACC)[3])         \
        : "r"(__float_as_uint(A0)), "r"(__float_as_uint(A1)),                    \
          "r"(__float_as_uint(A2)), "r"(__float_as_uint(A3)),                    \
          "r"(__float_as_uint(B0)), "r"(__float_as_uint(B1)))

__global__ __launch_bounds__(256, 2) void k_mma(
    const float* __restrict__ A, const float* __restrict__ B,
    const float* __restrict__ bias, float* __restrict__ C,
    int M, int N, int K, int act) {
    extern __shared__ float smem[];
    float* AsH = smem;                       // [128][AS_STRIDE]
    float* AsL = AsH + AS_ELEMS;
    float* BsH = AsL + AS_ELEMS;             // [32][BS_STRIDE]
    float* BsL = BsH + BS_ELEMS;

    const int tid = threadIdx.x;
    const int wid = tid >> 5;
    const int lane = tid & 31;
    const int warpM = wid >> 2;
    const int warpN = wid & 3;
    const int rowBase = blockIdx.y * 128;
    const int colBase = blockIdx.x * 128;

    const int lq = lane >> 2;
    const int lr = lane & 3;

    float acc[4][4][4];
#pragma unroll
    for (int i = 0; i < 4; i++)
#pragma unroll
        for (int j = 0; j < 4; j++)
#pragma unroll
            for (int r = 0; r < 4; r++) acc[i][j][r] = 0.f;

    const int aRow0 = tid >> 3;
    const int aCol4 = (tid & 7) << 2;
    const int bRow0 = tid >> 5;
    const int bCol4 = (tid & 31) << 2;

    for (int k0 = 0; k0 < K; k0 += 32) {
#pragma unroll
        for (int i = 0; i < 4; i++) {
            int r = aRow0 + i * 32;
            int gr = rowBase + r;
            if (gr >= M) gr = M - 1;
            float4 v = *(const float4*)(A + (size_t)gr * K + k0 + aCol4);
            float hx = to_tf32(v.x), hy = to_tf32(v.y), hz = to_tf32(v.z), hw = to_tf32(v.w);
            AsH[r * AS_STRIDE + aCol4 + 0] = hx;
            AsH[r * AS_STRIDE + aCol4 + 1] = hy;
            AsH[r * AS_STRIDE + aCol4 + 2] = hz;
            AsH[r * AS_STRIDE + aCol4 + 3] = hw;
            AsL[r * AS_STRIDE + aCol4 + 0] = to_tf32(v.x - hx);
            AsL[r * AS_STRIDE + aCol4 + 1] = to_tf32(v.y - hy);
            AsL[r * AS_STRIDE + aCol4 + 2] = to_tf32(v.z - hz);
            AsL[r * AS_STRIDE + aCol4 + 3] = to_tf32(v.w - hw);
        }
#pragma unroll
        for (int i = 0; i < 4; i++) {
            int r = bRow0 + i * 8;
            float4 v = *(const float4*)(B + (size_t)(k0 + r) * N + colBase + bCol4);
            float hx = to_tf32(v.x), hy = to_tf32(v.y), hz = to_tf32(v.z), hw = to_tf32(v.w);
            BsH[r * BS_STRIDE + bCol4 + 0] = hx;
            BsH[r * BS_STRIDE + bCol4 + 1] = hy;
            BsH[r * BS_STRIDE + bCol4 + 2] = hz;
            BsH[r * BS_STRIDE + bCol4 + 3] = hw;
            BsL[r * BS_STRIDE + bCol4 + 0] = to_tf32(v.x - hx);
            BsL[r * BS_STRIDE + bCol4 + 1] = to_tf32(v.y - hy);
            BsL[r * BS_STRIDE + bCol4 + 2] = to_tf32(v.z - hz);
            BsL[r * BS_STRIDE + bCol4 + 3] = to_tf32(v.w - hw);
        }
        __syncthreads();

#pragma unroll
        for (int kk = 0; kk < 4; kk++) {
            const int kb = kk * 8;
            float bh[4][2], bl[4][2];
#pragma unroll
            for (int nt = 0; nt < 4; nt++) {
                int c = warpN * 32 + nt * 8 + lq;
                bh[nt][0] = BsH[(kb + lr) * BS_STRIDE + c];
                bh[nt][1] = BsH[(kb + lr + 4) * BS_STRIDE + c];
                bl[nt][0] = BsL[(kb + lr) * BS_STRIDE + c];
                bl[nt][1] = BsL[(kb + lr + 4) * BS_STRIDE + c];
            }
#pragma unroll
            for (int mt = 0; mt < 4; mt++) {
                int r = warpM * 64 + mt * 16 + lq;
                int i00 = r * AS_STRIDE + kb + lr;
                int i10 = (r + 8) * AS_STRIDE + kb + lr;
                float ah0 = AsH[i00], ah1 = AsH[i10], ah2 = AsH[i00 + 4], ah3 = AsH[i10 + 4];
                float al0 = AsL[i00], al1 = AsL[i10], al2 = AsL[i00 + 4], al3 = AsL[i10 + 4];
#pragma unroll
                for (int nt = 0; nt < 4; nt++) {
                    MMA_TF32(acc[mt][nt], al0, al1, al2, al3, bh[nt][0], bh[nt][1]);
                    MMA_TF32(acc[mt][nt], ah0, ah1, ah2, ah3, bl[nt][0], bl[nt][1]);
                    MMA_TF32(acc[mt][nt], ah0, ah1, ah2, ah3, bh[nt][0], bh[nt][1]);
                }
            }
        }
        __syncthreads();
    }

#pragma unroll
    for (int mt = 0; mt < 4; mt++) {
        int r0 = rowBase + warpM * 64 + mt * 16 + lq;
#pragma unroll
        for (int nt = 0; nt < 4; nt++) {
            int c = colBase + warpN * 32 + nt * 8 + lr * 2;
            float b0 = bias ? bias[c] : 0.f;
            float b1 = bias ? bias[c + 1] : 0.f;
            if (r0 < M) {
                float v0 = acc[mt][nt][0] + b0;
                float v1 = acc[mt][nt][1] + b1;
                if (act) { v0 = fmaxf(v0, 0.f); v1 = fmaxf(v1, 0.f); }
                *(float2*)(C + (size_t)r0 * N + c) = make_float2(v0, v1);
            }
            if (r0 + 8 < M) {
                float v2 = acc[mt][nt][2] + b0;
                float v3 = acc[mt][nt][3] + b1;
                if (act) { v2 = fmaxf(v2, 0.f); v3 = fmaxf(v3, 0.f); }
                *(float2*)(C + (size_t)(r0 + 8) * N + c) = make_float2(v2, v3);
            }
        }
    }
}

// ---------------- per-node attention scalars ----------------
__global__ void k_es_ed(const float* __restrict__ a_src, const float* __restrict__ a_dst) {
    int n = blockIdx.x * (blockDim.x >> 5) + (threadIdx.x >> 5);
    int lane = threadIdx.x & 31;
    if (n >= NN) return;
    float4 hv = *(const float4*)(g_h + (size_t)n * DF + lane * 4);
    float4 as = *(const float4*)(a_src + lane * 4);
    float4 ad = *(const float4*)(a_dst + lane * 4);
    float s = hv.x * as.x + hv.y * as.y + hv.z * as.z + hv.w * as.w;
    float d = hv.x * ad.x + hv.y * ad.y + hv.z * ad.z + hv.w * ad.w;
#pragma unroll
    for (int o = 16; o > 0; o >>= 1) {
        s += __shfl_xor_sync(0xffffffff, s, o);
        d += __shfl_xor_sync(0xffffffff, d, o);
    }
    if (lane == 0) {
        g_es[n] = s;
        g_ed[n] = d;
    }
}

// ---------------- fused per-node softmax + aggregation (warp per node) ----------------
__global__ void k_node_aggr(const float* __restrict__ bias) {
    int n = blockIdx.x * (blockDim.x >> 5) + (threadIdx.x >> 5);
    int lane = threadIdx.x & 31;
    if (n >= NN) return;
    int r0 = g_rowstart[n];
    int r1 = g_rowstart[n + 1];
    float edn = g_ed[n];

    float m = -1e30f;
    for (int i = r0 + lane; i < r1; i += 32)
        m = fmaxf(m, leaky(g_es[g_csr[i]] + edn));
#pragma unroll
    for (int o = 16; o > 0; o >>= 1)
        m = fmaxf(m, __shfl_xor_sync(0xffffffff, m, o));

    float s = 0.f;
    for (int i = r0 + lane; i < r1; i += 32)
        s += expf(leaky(g_es[g_csr[i]] + edn) - m);
#pragma unroll
    for (int o = 16; o > 0; o >>= 1)
        s += __shfl_xor_sync(0xffffffff, s, o);
    float inv = 1.f / s;

    float4 acc = make_float4(0.f, 0.f, 0.f, 0.f);
    for (int i = r0; i < r1; i++) {
        int src = g_csr[i];
        float w = expf(leaky(g_es[src] + edn) - m) * inv;
        float4 hv = *(const float4*)(g_h + (size_t)src * DF + lane * 4);
        acc.x += w * hv.x;
        acc.y += w * hv.y;
        acc.z += w * hv.z;
        acc.w += w * hv.w;
    }
    float4 bv = *(const float4*)(bias + lane * 4);
    float4 r;
    r.x = leaky(acc.x + bv.x);
    r.y = leaky(acc.y + bv.y);
    r.z = leaky(acc.z + bv.z);
    r.w = leaky(acc.w + bv.w);
    *(float4*)(g_x + (size_t)n * DF + lane * 4) = r;
}

// ---------------- output head ----------------
__global__ void k_out(const float* __restrict__ Y, const float* __restrict__ Wout,
                      const float* __restrict__ bout, float* __restrict__ out) {
    int n = blockIdx.x * (blockDim.x >> 5) + (threadIdx.x >> 5);
    int lane = threadIdx.x & 31;
    if (n >= NN) return;
    float acc0 = 0.f, acc1 = 0.f, acc2 = 0.f, acc3 = 0.f;
    const float* y = Y + (size_t)n * DLIN;
    for (int k = lane; k < DLIN; k += 32) {
        float v = y[k];
        const float4 wv = *(const float4*)(Wout + k * 4);
        acc0 += v * wv.x;
        acc1 += v * wv.y;
        acc2 += v * wv.z;
        acc3 += v * wv.w;
    }
#pragma unroll
    for (int o = 16; o > 0; o >>= 1) {
        acc0 += __shfl_xor_sync(0xffffffff, acc0, o);
        acc1 += __shfl_xor_sync(0xffffffff, acc1, o);
        acc2 += __shfl_xor_sync(0xffffffff, acc2, o);
        acc3 += __shfl_xor_sync(0xffffffff, acc3, o);
    }
    if (lane == 0) {
        float4 r;
        r.x = acc0 + bout[0];
        r.y = acc1 + bout[1];
        r.z = acc2 + bout[2];
        r.w = acc3 + bout[3];
        *(float4*)(out + (size_t)n * 4) = r;
    }
}

extern "C" void kernel_launch(void* const* d_in, const int* in_sizes, int n_in,
                              void* d_out, int out_size) {
    const float *x, *conv_W, *conv_as, *conv_ad, *conv_b;
    const float *lin_W0, *lin_b0, *lin_W1, *lin_b1, *lin_W2, *lin_b2, *lin_Wout, *lin_bout;
    const void* ei;

    if (in_sizes[0] == NN * DF) {
        x        = (const float*)d_in[0];
        ei       = d_in[1];
        conv_W   = (const float*)d_in[2];
        conv_as  = (const float*)d_in[3];
        conv_ad  = (const float*)d_in[4];
        conv_b   = (const float*)d_in[5];
        lin_W0   = (const float*)d_in[6];
        lin_b0   = (const float*)d_in[7];
        lin_W1   = (const float*)d_in[8];
        lin_b1   = (const float*)d_in[9];
        lin_W2   = (const float*)d_in[10];
        lin_b2   = (const float*)d_in[11];
        lin_Wout = (const float*)d_in[12];
        lin_bout = (const float*)d_in[13];
    } else {
        conv_W   = (const float*)d_in[0];
        conv_ad  = (const float*)d_in[1];
        conv_as  = (const float*)d_in[2];
        conv_b   = (const float*)d_in[3];
        ei       = d_in[4];
        lin_W0   = (const float*)d_in[5];
        lin_W1   = (const float*)d_in[6];
        lin_W2   = (const float*)d_in[7];
        lin_Wout = (const float*)d_in[8];
        lin_b0   = (const float*)d_in[9];
        lin_b1   = (const float*)d_in[10];
        lin_b2   = (const float*)d_in[11];
        lin_bout = (const float*)d_in[12];
        x        = (const float*)d_in[13];
    }
    float* out = (float*)d_out;

    void *p_x, *p_h, *p_y0, *p_y1;
    cudaGetSymbolAddress(&p_x, g_x);
    cudaGetSymbolAddress(&p_h, g_h);
    cudaGetSymbolAddress(&p_y0, g_y0);
    cudaGetSymbolAddress(&p_y1, g_y1);

    static int smem_set = 0;
    if (!smem_set) {
        cudaFuncSetAttribute(k_mma, cudaFuncAttributeMaxDynamicSharedMemorySize, SMEM_MMA);
        smem_set = 1;
    }

    // edges + CSR (once per launch)
    k_detect_dtype<<<1, 32>>>((const int*)ei);
    k_build_edges<<<(NEL + 255) / 256, 256>>>(ei);
    k_zero_deg<<<(NN + 255) / 256, 256>>>();
    k_hist<<<(NEL + 255) / 256, 256>>>();
    k_scan1<<<NBLK, 1024>>>();
    k_scan2<<<1, 32>>>();
    k_scan3<<<(NN + 255) / 256, 256>>>();
    k_scatter<<<(NEL + 255) / 256, 256>>>();

    dim3 grid128(1, (NN + 127) / 128);
    dim3 grid512(DLIN / 128, (NN + 127) / 128);
    const int wpb = 8;
    const int nodeBlocks = (NN + wpb - 1) / wpb;

    const float* curX = x;
    for (int layer = 0; layer < 3; layer++) {
        const float* W  = conv_W + (size_t)layer * DF * DF;
        const float* as = conv_as + (size_t)layer * DF;
        const float* ad = conv_ad + (size_t)layer * DF;
        const float* b  = conv_b + (size_t)layer * DF;

        k_mma<<<grid128, 256, SMEM_MMA>>>(curX, W, nullptr, (float*)p_h, NN, DF, DF, 0);
        k_es_ed<<<nodeBlocks, wpb * 32>>>(as, ad);
        k_node_aggr<<<nodeBlocks, wpb * 32>>>(b);
        curX = (const float*)p_x;
    }

    k_mma<<<grid512, 256, SMEM_MMA>>>((const float*)p_x, lin_W0, lin_b0, (float*)p_y0, NN, DLIN, DF, 1);
    k_mma<<<grid512, 256, SMEM_MMA>>>((const float*)p_y0, lin_W1, lin_b1, (float*)p_y1, NN, DLIN, DLIN, 1);
    k_mma<<<grid512, 256, SMEM_MMA>>>((const float*)p_y1, lin_W2, lin_b2, (float*)p_y0, NN, DLIN, DLIN, 1);
    k_out<<<nodeBlocks, wpb * 32>>>((const float*)p_y0, lin_Wout, lin_bout, out);
}

// round 14
// speedup vs baseline: 2.5270x; 1.3400x over previous
#include <cuda_runtime.h>
#include <cuda_bf16.h>
#include <math.h>

#define NN 50000
#define NE 800000
#define NEL 850000
#define DF 128
#define DLIN 512
#define DOUT 4
#define NBLK 49   // ceil(NN/1024)

// ---------------- device scratch ----------------
__device__ __align__(16) float g_x[NN * DF];
__device__ __align__(16) float g_h[NN * DF];
__device__ __align__(16) float g_es[NN];
__device__ __align__(16) float g_ed[NN];
__device__ __align__(16) int g_src[NEL];
__device__ __align__(16) int g_dst[NEL];
__device__ __align__(16) float g_y0[NN * DLIN];
__device__ __align__(16) float g_y1[NN * DLIN];
// CSR
__device__ __align__(16) int g_deg[NN];
__device__ __align__(16) int g_incl[NN];
__device__ __align__(16) int g_bsum[NBLK];
__device__ __align__(16) int g_boff[NBLK];
__device__ __align__(16) int g_rowstart[NN + 1];
__device__ __align__(16) int g_cursor[NN];
__device__ __align__(16) int g_csr[NEL];
__device__ int g_is64;

// ---------------- helpers ----------------
__device__ __forceinline__ float leaky(float v) { return v > 0.f ? v : 0.2f * v; }

// pack(lo_elem -> low16, hi_elem -> high16)
__device__ __forceinline__ unsigned pack_bf16x2(float e_lo, float e_hi) {
    unsigned r;
    asm("cvt.rn.bf16x2.f32 %0, %1, %2;" : "=r"(r) : "f"(e_hi), "f"(e_lo));
    return r;
}
// split v into bf16 hi + bf16 lo (residual)
__device__ __forceinline__ void split_bf16(float v, float& hi, float& lo) {
    __nv_bfloat16 h = __float2bfloat16_rn(v);
    hi = __bfloat162float(h);
    lo = v - hi;
}

// ---------------- edge dtype probe ----------------
__global__ void k_detect_dtype(const int* __restrict__ ei32) {
    if (threadIdx.x != 0 || blockIdx.x != 0) return;
    int zeros = 0;
    for (int i = 0; i < 256; i++)
        if (ei32[2 * i + 1] == 0) zeros++;
    g_is64 = (zeros >= 250) ? 1 : 0;
}

__global__ void k_build_edges(const void* __restrict__ ei) {
    int i = blockIdx.x * blockDim.x + threadIdx.x;
    if (i >= NEL) return;
    int s, d;
    if (i < NE) {
        if (g_is64) {
            const long long* p = (const long long*)ei;
            s = (int)p[i];
            d = (int)p[NE + i];
        } else {
            const int* p = (const int*)ei;
            s = p[i];
            d = p[NE + i];
        }
        s = min(max(s, 0), NN - 1);
        d = min(max(d, 0), NN - 1);
    } else {
        s = i - NE;
        d = i - NE;
    }
    g_src[i] = s;
    g_dst[i] = d;
}

// ---------------- CSR build ----------------
__global__ void k_zero_deg() {
    int i = blockIdx.x * blockDim.x + threadIdx.x;
    if (i < NN) g_deg[i] = 0;
}
__global__ void k_hist() {
    int e = blockIdx.x * blockDim.x + threadIdx.x;
    if (e >= NEL) return;
    atomicAdd(&g_deg[g_dst[e]], 1);
}
__global__ void k_scan1() {
    __shared__ int sm[1024];
    int i = blockIdx.x * 1024 + threadIdx.x;
    int v = (i < NN) ? g_deg[i] : 0;
    sm[threadIdx.x] = v;
    __syncthreads();
    for (int off = 1; off < 1024; off <<= 1) {
        int t = (threadIdx.x >= off) ? sm[threadIdx.x - off] : 0;
        __syncthreads();
        sm[threadIdx.x] += t;
        __syncthreads();
    }
    if (i < NN) g_incl[i] = sm[threadIdx.x];
    if (threadIdx.x == 1023) g_bsum[blockIdx.x] = sm[1023];
}
__global__ void k_scan2() {
    if (threadIdx.x == 0 && blockIdx.x == 0) {
        int run = 0;
        for (int b = 0; b < NBLK; b++) {
            int t = g_bsum[b];
            g_boff[b] = run;
            run += t;
        }
    }
}
__global__ void k_scan3() {
    int i = blockIdx.x * blockDim.x + threadIdx.x;
    if (i < NN) {
        int rs = g_incl[i] - g_deg[i] + g_boff[i >> 10];
        g_rowstart[i] = rs;
        g_cursor[i] = rs;
    }
    if (i == 0) g_rowstart[NN] = NEL;
}
__global__ void k_scatter() {
    int e = blockIdx.x * blockDim.x + threadIdx.x;
    if (e >= NEL) return;
    int pos = atomicAdd(&g_cursor[g_dst[e]], 1);
    g_csr[pos] = g_src[e];
}

// ---------------- split-BF16 tensor-core GEMM (m16n8k16, 3-term) ----------------
// C[M,N] = A[M,K] @ B[K,N] (+bias)(+relu). BM=128 BN=128 BK=32.
// smem words are bf16x2 (pair along K). A: [128][20] u32; B: [16][136] u32.
#define AW_STRIDE 20    // 16 data words + pad; lq*20+lr covers 32 banks
#define BW_STRIDE 136   // ≡8 mod 32; lr*8*... distinct
#define AW_ELEMS (128 * AW_STRIDE)
#define BW_ELEMS (16 * BW_STRIDE)

#define MMA_BF16(ACC, A0, A1, A2, A3, B0, B1)                                    \
    asm volatile(                                                                 \
        "mma.sync.aligned.m16n8k16.row.col.f32.bf16.bf16.f32 "                    \
        "{%0,%1,%2,%3}, {%4,%5,%6,%7}, {%8,%9}, {%0,%1,%2,%3};"                   \
        : "+f"((ACC)[0]), "+f"((ACC)[1]), "+f"((ACC)[2]), "+f"((ACC)[3])          \
        : "r"(A0), "r"(A1), "r"(A2), "r"(A3), "r"(B0), "r"(B1))

__global__ __launch_bounds__(256, 2) void k_mma(
    const float* __restrict__ A, const float* __restrict__ B,
    const float* __restrict__ bias, float* __restrict__ C,
    int M, int N, int K, int act) {
    __shared__ unsigned AsH[AW_ELEMS], AsL[AW_ELEMS];
    __shared__ unsigned BsH[BW_ELEMS], BsL[BW_ELEMS];

    const int tid = threadIdx.x;
    const int wid = tid >> 5;
    const int lane = tid & 31;
    const int warpM = wid >> 2;
    const int warpN = wid & 3;
    const int rowBase = blockIdx.y * 128;
    const int colBase = blockIdx.x * 128;

    const int lq = lane >> 2;
    const int lr = lane & 3;

    float acc[4][4][4];
#pragma unroll
    for (int i = 0; i < 4; i++)
#pragma unroll
        for (int j = 0; j < 4; j++)
#pragma unroll
            for (int r = 0; r < 4; r++) acc[i][j][r] = 0.f;

    const int aRow0 = tid >> 3;              // 0..31 (+32 steps)
    const int aCol4 = (tid & 7) << 2;        // float col 0,4,..,28
    const int aWord = aCol4 >> 1;            // word col 0,2,..,14
    const int bK2_0 = tid >> 5;              // k-pair 0..7 (+8)
    const int bCol4 = (tid & 31) << 2;       // n col 0..124

    for (int k0 = 0; k0 < K; k0 += 32) {
        // ---- A tile 128x32 -> hi/lo bf16x2 words ----
#pragma unroll
        for (int i = 0; i < 4; i++) {
            int r = aRow0 + i * 32;
            int gr = rowBase + r;
            if (gr >= M) gr = M - 1;
            float4 v = *(const float4*)(A + (size_t)gr * K + k0 + aCol4);
            float hx, lx, hy, ly, hz, lz, hw, lw;
            split_bf16(v.x, hx, lx);
            split_bf16(v.y, hy, ly);
            split_bf16(v.z, hz, lz);
            split_bf16(v.w, hw, lw);
            uint2 hwords = make_uint2(pack_bf16x2(hx, hy), pack_bf16x2(hz, hw));
            uint2 lwords = make_uint2(pack_bf16x2(lx, ly), pack_bf16x2(lz, lw));
            *(uint2*)&AsH[r * AW_STRIDE + aWord] = hwords;
            *(uint2*)&AsL[r * AW_STRIDE + aWord] = lwords;
        }
        // ---- B tile 32x128 -> word[k2][n] = pack(B[2k2][n], B[2k2+1][n]) ----
#pragma unroll
        for (int i = 0; i < 2; i++) {
            int k2 = bK2_0 + i * 8;
            const float* p0 = B + (size_t)(k0 + 2 * k2) * N + colBase + bCol4;
            const float* p1 = p0 + N;
            float4 v0 = *(const float4*)p0;
            float4 v1 = *(const float4*)p1;
            float h0x, l0x, h0y, l0y, h0z, l0z, h0w, l0w;
            float h1x, l1x, h1y, l1y, h1z, l1z, h1w, l1w;
            split_bf16(v0.x, h0x, l0x); split_bf16(v0.y, h0y, l0y);
            split_bf16(v0.z, h0z, l0z); split_bf16(v0.w, h0w, l0w);
            split_bf16(v1.x, h1x, l1x); split_bf16(v1.y, h1y, l1y);
            split_bf16(v1.z, h1z, l1z); split_bf16(v1.w, h1w, l1w);
            uint4 hw4 = make_uint4(pack_bf16x2(h0x, h1x), pack_bf16x2(h0y, h1y),
                                   pack_bf16x2(h0z, h1z), pack_bf16x2(h0w, h1w));
            uint4 lw4 = make_uint4(pack_bf16x2(l0x, l1x), pack_bf16x2(l0y, l1y),
                                   pack_bf16x2(l0z, l1z), pack_bf16x2(l0w, l1w));
            *(uint4*)&BsH[k2 * BW_STRIDE + bCol4] = hw4;
            *(uint4*)&BsL[k2 * BW_STRIDE + bCol4] = lw4;
        }
        __syncthreads();

        // ---- compute: two k16 chunks per k0 ----
#pragma unroll
        for (int kk = 0; kk < 2; kk++) {
            const int kw = kk * 8;   // word base for this k16 chunk
            unsigned bh[4][2], bl[4][2];
#pragma unroll
            for (int nt = 0; nt < 4; nt++) {
                int c = warpN * 32 + nt * 8 + lq;
                bh[nt][0] = BsH[(kw + lr) * BW_STRIDE + c];
                bh[nt][1] = BsH[(kw + lr + 4) * BW_STRIDE + c];
                bl[nt][0] = BsL[(kw + lr) * BW_STRIDE + c];
                bl[nt][1] = BsL[(kw + lr + 4) * BW_STRIDE + c];
            }
#pragma unroll
            for (int mt = 0; mt < 4; mt++) {
                int r = warpM * 64 + mt * 16 + lq;
                int i0 = r * AW_STRIDE + kw + lr;
                int i1 = (r + 8) * AW_STRIDE + kw + lr;
                unsigned ah0 = AsH[i0], ah1 = AsH[i1], ah2 = AsH[i0 + 4], ah3 = AsH[i1 + 4];
                unsigned al0 = AsL[i0], al1 = AsL[i1], al2 = AsL[i0 + 4], al3 = AsL[i1 + 4];
#pragma unroll
                for (int nt = 0; nt < 4; nt++) {
                    MMA_BF16(acc[mt][nt], al0, al1, al2, al3, bh[nt][0], bh[nt][1]);
                    MMA_BF16(acc[mt][nt], ah0, ah1, ah2, ah3, bl[nt][0], bl[nt][1]);
                    MMA_BF16(acc[mt][nt], ah0, ah1, ah2, ah3, bh[nt][0], bh[nt][1]);
                }
            }
        }
        __syncthreads();
    }

#pragma unroll
    for (int mt = 0; mt < 4; mt++) {
        int r0 = rowBase + warpM * 64 + mt * 16 + lq;
#pragma unroll
        for (int nt = 0; nt < 4; nt++) {
            int c = colBase + warpN * 32 + nt * 8 + lr * 2;
            float b0 = bias ? bias[c] : 0.f;
            float b1 = bias ? bias[c + 1] : 0.f;
            if (r0 < M) {
                float v0 = acc[mt][nt][0] + b0;
                float v1 = acc[mt][nt][1] + b1;
                if (act) { v0 = fmaxf(v0, 0.f); v1 = fmaxf(v1, 0.f); }
                *(float2*)(C + (size_t)r0 * N + c) = make_float2(v0, v1);
            }
            if (r0 + 8 < M) {
                float v2 = acc[mt][nt][2] + b0;
                float v3 = acc[mt][nt][3] + b1;
                if (act) { v2 = fmaxf(v2, 0.f); v3 = fmaxf(v3, 0.f); }
                *(float2*)(C + (size_t)(r0 + 8) * N + c) = make_float2(v2, v3);
            }
        }
    }
}

// ---------------- per-node attention scalars ----------------
__global__ void k_es_ed(const float* __restrict__ a_src, const float* __restrict__ a_dst) {
    int n = blockIdx.x * (blockDim.x >> 5) + (threadIdx.x >> 5);
    int lane = threadIdx.x & 31;
    if (n >= NN) return;
    float4 hv = *(const float4*)(g_h + (size_t)n * DF + lane * 4);
    float4 as = *(const float4*)(a_src + lane * 4);
    float4 ad = *(const float4*)(a_dst + lane * 4);
    float s = hv.x * as.x + hv.y * as.y + hv.z * as.z + hv.w * as.w;
    float d = hv.x * ad.x + hv.y * ad.y + hv.z * ad.z + hv.w * ad.w;
#pragma unroll
    for (int o = 16; o > 0; o >>= 1) {
        s += __shfl_xor_sync(0xffffffff, s, o);
        d += __shfl_xor_sync(0xffffffff, d, o);
    }
    if (lane == 0) {
        g_es[n] = s;
        g_ed[n] = d;
    }
}

// ---------------- fused per-node softmax + aggregation (warp per node) ----------------
__global__ void k_node_aggr(const float* __restrict__ bias) {
    int n = blockIdx.x * (blockDim.x >> 5) + (threadIdx.x >> 5);
    int lane = threadIdx.x & 31;
    if (n >= NN) return;
    int r0 = g_rowstart[n];
    int r1 = g_rowstart[n + 1];
    float edn = g_ed[n];

    float m = -1e30f;
    for (int i = r0 + lane; i < r1; i += 32)
        m = fmaxf(m, leaky(g_es[g_csr[i]] + edn));
#pragma unroll
    for (int o = 16; o > 0; o >>= 1)
        m = fmaxf(m, __shfl_xor_sync(0xffffffff, m, o));

    float s = 0.f;
    for (int i = r0 + lane; i < r1; i += 32)
        s += expf(leaky(g_es[g_csr[i]] + edn) - m);
#pragma unroll
    for (int o = 16; o > 0; o >>= 1)
        s += __shfl_xor_sync(0xffffffff, s, o);
    float inv = 1.f / s;

    float4 acc = make_float4(0.f, 0.f, 0.f, 0.f);
    for (int i = r0; i < r1; i++) {
        int src = g_csr[i];
        float w = expf(leaky(g_es[src] + edn) - m) * inv;
        float4 hv = *(const float4*)(g_h + (size_t)src * DF + lane * 4);
        acc.x += w * hv.x;
        acc.y += w * hv.y;
        acc.z += w * hv.z;
        acc.w += w * hv.w;
    }
    float4 bv = *(const float4*)(bias + lane * 4);
    float4 r;
    r.x = leaky(acc.x + bv.x);
    r.y = leaky(acc.y + bv.y);
    r.z = leaky(acc.z + bv.z);
    r.w = leaky(acc.w + bv.w);
    *(float4*)(g_x + (size_t)n * DF + lane * 4) = r;
}

// ---------------- output head ----------------
__global__ void k_out(const float* __restrict__ Y, const float* __restrict__ Wout,
                      const float* __restrict__ bout, float* __restrict__ out) {
    int n = blockIdx.x * (blockDim.x >> 5) + (threadIdx.x >> 5);
    int lane = threadIdx.x & 31;
    if (n >= NN) return;
    float acc0 = 0.f, acc1 = 0.f, acc2 = 0.f, acc3 = 0.f;
    const float* y = Y + (size_t)n * DLIN;
    for (int k = lane; k < DLIN; k += 32) {
        float v = y[k];
        const float4 wv = *(const float4*)(Wout + k * 4);
        acc0 += v * wv.x;
        acc1 += v * wv.y;
        acc2 += v * wv.z;
        acc3 += v * wv.w;
    }
#pragma unroll
    for (int o = 16; o > 0; o >>= 1) {
        acc0 += __shfl_xor_sync(0xffffffff, acc0, o);
        acc1 += __shfl_xor_sync(0xffffffff, acc1, o);
        acc2 += __shfl_xor_sync(0xffffffff, acc2, o);
        acc3 += __shfl_xor_sync(0xffffffff, acc3, o);
    }
    if (lane == 0) {
        float4 r;
        r.x = acc0 + bout[0];
        r.y = acc1 + bout[1];
        r.z = acc2 + bout[2];
        r.w = acc3 + bout[3];
        *(float4*)(out + (size_t)n * 4) = r;
    }
}

extern "C" void kernel_launch(void* const* d_in, const int* in_sizes, int n_in,
                              void* d_out, int out_size) {
    const float *x, *conv_W, *conv_as, *conv_ad, *conv_b;
    const float *lin_W0, *lin_b0, *lin_W1, *lin_b1, *lin_W2, *lin_b2, *lin_Wout, *lin_bout;
    const void* ei;

    if (in_sizes[0] == NN * DF) {
        x        = (const float*)d_in[0];
        ei       = d_in[1];
        conv_W   = (const float*)d_in[2];
        conv_as  = (const float*)d_in[3];
        conv_ad  = (const float*)d_in[4];
        conv_b   = (const float*)d_in[5];
        lin_W0   = (const float*)d_in[6];
        lin_b0   = (const float*)d_in[7];
        lin_W1   = (const float*)d_in[8];
        lin_b1   = (const float*)d_in[9];
        lin_W2   = (const float*)d_in[10];
        lin_b2   = (const float*)d_in[11];
        lin_Wout = (const float*)d_in[12];
        lin_bout = (const float*)d_in[13];
    } else {
        conv_W   = (const float*)d_in[0];
        conv_ad  = (const float*)d_in[1];
        conv_as  = (const float*)d_in[2];
        conv_b   = (const float*)d_in[3];
        ei       = d_in[4];
        lin_W0   = (const float*)d_in[5];
        lin_W1   = (const float*)d_in[6];
        lin_W2   = (const float*)d_in[7];
        lin_Wout = (const float*)d_in[8];
        lin_b0   = (const float*)d_in[9];
        lin_b1   = (const float*)d_in[10];
        lin_b2   = (const float*)d_in[11];
        lin_bout = (const float*)d_in[12];
        x        = (const float*)d_in[13];
    }
    float* out = (float*)d_out;

    void *p_x, *p_h, *p_y0, *p_y1;
    cudaGetSymbolAddress(&p_x, g_x);
    cudaGetSymbolAddress(&p_h, g_h);
    cudaGetSymbolAddress(&p_y0, g_y0);
    cudaGetSymbolAddress(&p_y1, g_y1);

    // edges + CSR (once per launch)
    k_detect_dtype<<<1, 32>>>((const int*)ei);
    k_build_edges<<<(NEL + 255) / 256, 256>>>(ei);
    k_zero_deg<<<(NN + 255) / 256, 256>>>();
    k_hist<<<(NEL + 255) / 256, 256>>>();
    k_scan1<<<NBLK, 1024>>>();
    k_scan2<<<1, 32>>>();
    k_scan3<<<(NN + 255) / 256, 256>>>();
    k_scatter<<<(NEL + 255) / 256, 256>>>();

    dim3 grid128(1, (NN + 127) / 128);
    dim3 grid512(DLIN / 128, (NN + 127) / 128);
    const int wpb = 8;
    const int nodeBlocks = (NN + wpb - 1) / wpb;

    const float* curX = x;
    for (int layer = 0; layer < 3; layer++) {
        const float* W  = conv_W + (size_t)layer * DF * DF;
        const float* as = conv_as + (size_t)layer * DF;
        const float* ad = conv_ad + (size_t)layer * DF;
        const float* b  = conv_b + (size_t)layer * DF;

        k_mma<<<grid128, 256>>>(curX, W, nullptr, (float*)p_h, NN, DF, DF, 0);
        k_es_ed<<<nodeBlocks, wpb * 32>>>(as, ad);
        k_node_aggr<<<nodeBlocks, wpb * 32>>>(b);
        curX = (const float*)p_x;
    }

    k_mma<<<grid512, 256>>>((const float*)p_x, lin_W0, lin_b0, (float*)p_y0, NN, DLIN, DF, 1);
    k_mma<<<grid512, 256>>>((const float*)p_y0, lin_W1, lin_b1, (float*)p_y1, NN, DLIN, DLIN, 1);
    k_mma<<<grid512, 256>>>((const float*)p_y1, lin_W2, lin_b2, (float*)p_y0, NN, DLIN, DLIN, 1);
    k_out<<<nodeBlocks, wpb * 32>>>((const float*)p_y0, lin_Wout, lin_bout, out);
}

// round 16
// speedup vs baseline: 2.6621x; 1.0535x over previous
#include <cuda_runtime.h>
#include <cuda_bf16.h>
#include <math.h>

#define NN 50000
#define NE 800000
#define NEL 850000
#define DF 128
#define DLIN 512
#define DOUT 4
#define NBLK 49   // ceil(NN/1024)

// ---------------- device scratch ----------------
__device__ __align__(16) float g_x[NN * DF];
__device__ __align__(16) float g_h[NN * DF];
__device__ __align__(16) float g_es[NN];
__device__ __align__(16) float g_ed[NN];
__device__ __align__(16) int g_src[NEL];
__device__ __align__(16) int g_dst[NEL];
__device__ __align__(16) float g_y0[NN * DLIN];
__device__ __align__(16) float g_y1[NN * DLIN];
// CSR
__device__ __align__(16) int g_deg[NN];
__device__ __align__(16) int g_incl[NN];
__device__ __align__(16) int g_bsum[NBLK];
__device__ __align__(16) int g_boff[NBLK];
__device__ __align__(16) int g_rowstart[NN + 1];
__device__ __align__(16) int g_cursor[NN];
__device__ __align__(16) int g_csr[NEL];
__device__ int g_is64;

// ---------------- helpers ----------------
__device__ __forceinline__ float leaky(float v) { return v > 0.f ? v : 0.2f * v; }

__device__ __forceinline__ unsigned pack_bf16x2(float e_lo, float e_hi) {
    unsigned r;
    asm("cvt.rn.bf16x2.f32 %0, %1, %2;" : "=r"(r) : "f"(e_hi), "f"(e_lo));
    return r;
}
__device__ __forceinline__ void split_bf16(float v, float& hi, float& lo) {
    __nv_bfloat16 h = __float2bfloat16_rn(v);
    hi = __bfloat162float(h);
    lo = v - hi;
}

// ---------------- edge dtype probe ----------------
__global__ void k_detect_dtype(const int* __restrict__ ei32) {
    if (threadIdx.x != 0 || blockIdx.x != 0) return;
    int zeros = 0;
    for (int i = 0; i < 256; i++)
        if (ei32[2 * i + 1] == 0) zeros++;
    g_is64 = (zeros >= 250) ? 1 : 0;
}

__global__ void k_build_edges(const void* __restrict__ ei) {
    int i = blockIdx.x * blockDim.x + threadIdx.x;
    if (i >= NEL) return;
    int s, d;
    if (i < NE) {
        if (g_is64) {
            const long long* p = (const long long*)ei;
            s = (int)p[i];
            d = (int)p[NE + i];
        } else {
            const int* p = (const int*)ei;
            s = p[i];
            d = p[NE + i];
        }
        s = min(max(s, 0), NN - 1);
        d = min(max(d, 0), NN - 1);
    } else {
        s = i - NE;
        d = i - NE;
    }
    g_src[i] = s;
    g_dst[i] = d;
}

// ---------------- CSR build ----------------
__global__ void k_zero_deg() {
    int i = blockIdx.x * blockDim.x + threadIdx.x;
    if (i < NN) g_deg[i] = 0;
}
__global__ void k_hist() {
    int e = blockIdx.x * blockDim.x + threadIdx.x;
    if (e >= NEL) return;
    atomicAdd(&g_deg[g_dst[e]], 1);
}
__global__ void k_scan1() {
    __shared__ int sm[1024];
    int i = blockIdx.x * 1024 + threadIdx.x;
    int v = (i < NN) ? g_deg[i] : 0;
    sm[threadIdx.x] = v;
    __syncthreads();
    for (int off = 1; off < 1024; off <<= 1) {
        int t = (threadIdx.x >= off) ? sm[threadIdx.x - off] : 0;
        __syncthreads();
        sm[threadIdx.x] += t;
        __syncthreads();
    }
    if (i < NN) g_incl[i] = sm[threadIdx.x];
    if (threadIdx.x == 1023) g_bsum[blockIdx.x] = sm[1023];
}
__global__ void k_scan2() {
    if (threadIdx.x == 0 && blockIdx.x == 0) {
        int run = 0;
        for (int b = 0; b < NBLK; b++) {
            int t = g_bsum[b];
            g_boff[b] = run;
            run += t;
        }
    }
}
__global__ void k_scan3() {
    int i = blockIdx.x * blockDim.x + threadIdx.x;
    if (i < NN) {
        int rs = g_incl[i] - g_deg[i] + g_boff[i >> 10];
        g_rowstart[i] = rs;
        g_cursor[i] = rs;
    }
    if (i == 0) g_rowstart[NN] = NEL;
}
__global__ void k_scatter() {
    int e = blockIdx.x * blockDim.x + threadIdx.x;
    if (e >= NEL) return;
    int pos = atomicAdd(&g_cursor[g_dst[e]], 1);
    g_csr[pos] = g_src[e];
}

// ---------------- split-BF16 tensor-core GEMM (m16n8k16, 3-term, reg-prefetch) ----------------
#define AW_STRIDE 20
#define BW_STRIDE 136
#define AW_ELEMS (128 * AW_STRIDE)
#define BW_ELEMS (16 * BW_STRIDE)

#define MMA_BF16(ACC, A0, A1, A2, A3, B0, B1)                                    \
    asm volatile(                                                                 \
        "mma.sync.aligned.m16n8k16.row.col.f32.bf16.bf16.f32 "                    \
        "{%0,%1,%2,%3}, {%4,%5,%6,%7}, {%8,%9}, {%0,%1,%2,%3};"                   \
        : "+f"((ACC)[0]), "+f"((ACC)[1]), "+f"((ACC)[2]), "+f"((ACC)[3])          \
        : "r"(A0), "r"(A1), "r"(A2), "r"(A3), "r"(B0), "r"(B1))

__global__ __launch_bounds__(256, 2) void k_mma(
    const float* __restrict__ A, const float* __restrict__ B,
    const float* __restrict__ bias, float* __restrict__ C,
    int M, int N, int K, int act) {
    __shared__ unsigned AsH[AW_ELEMS], AsL[AW_ELEMS];
    __shared__ unsigned BsH[BW_ELEMS], BsL[BW_ELEMS];

    const int tid = threadIdx.x;
    const int wid = tid >> 5;
    const int lane = tid & 31;
    const int warpM = wid >> 2;
    const int warpN = wid & 3;
    const int rowBase = blockIdx.y * 128;
    const int colBase = blockIdx.x * 128;

    const int lq = lane >> 2;
    const int lr = lane & 3;

    float acc[4][4][4];
#pragma unroll
    for (int i = 0; i < 4; i++)
#pragma unroll
        for (int j = 0; j < 4; j++)
#pragma unroll
            for (int r = 0; r < 4; r++) acc[i][j][r] = 0.f;

    const int aRow0 = tid >> 3;
    const int aCol4 = (tid & 7) << 2;
    const int aWord = aCol4 >> 1;
    const int bK2_0 = tid >> 5;
    const int bCol4 = (tid & 31) << 2;

    // clamped A row addresses (fixed across k0)
    int aRowG[4];
#pragma unroll
    for (int i = 0; i < 4; i++) {
        int gr = rowBase + aRow0 + i * 32;
        if (gr >= M) gr = M - 1;
        aRowG[i] = gr;
    }

    // ---- prologue: prefetch tile 0 into registers ----
    float4 aP[4];
    float4 bP0[2], bP1[2];
#pragma unroll
    for (int i = 0; i < 4; i++)
        aP[i] = *(const float4*)(A + (size_t)aRowG[i] * K + aCol4);
#pragma unroll
    for (int i = 0; i < 2; i++) {
        int k2 = bK2_0 + i * 8;
        const float* p0 = B + (size_t)(2 * k2) * N + colBase + bCol4;
        bP0[i] = *(const float4*)p0;
        bP1[i] = *(const float4*)(p0 + N);
    }

    for (int k0 = 0; k0 < K; k0 += 32) {
        // ---- convert + STS from prefetch registers ----
#pragma unroll
        for (int i = 0; i < 4; i++) {
            int r = aRow0 + i * 32;
            float4 v = aP[i];
            float hx, lx, hy, ly, hz, lz, hw, lw;
            split_bf16(v.x, hx, lx);
            split_bf16(v.y, hy, ly);
            split_bf16(v.z, hz, lz);
            split_bf16(v.w, hw, lw);
            *(uint2*)&AsH[r * AW_STRIDE + aWord] = make_uint2(pack_bf16x2(hx, hy), pack_bf16x2(hz, hw));
            *(uint2*)&AsL[r * AW_STRIDE + aWord] = make_uint2(pack_bf16x2(lx, ly), pack_bf16x2(lz, lw));
        }
#pragma unroll
        for (int i = 0; i < 2; i++) {
            int k2 = bK2_0 + i * 8;
            float4 v0 = bP0[i];
            float4 v1 = bP1[i];
            float h0x, l0x, h0y, l0y, h0z, l0z, h0w, l0w;
            float h1x, l1x, h1y, l1y, h1z, l1z, h1w, l1w;
            split_bf16(v0.x, h0x, l0x); split_bf16(v0.y, h0y, l0y);
            split_bf16(v0.z, h0z, l0z); split_bf16(v0.w, h0w, l0w);
            split_bf16(v1.x, h1x, l1x); split_bf16(v1.y, h1y, l1y);
            split_bf16(v1.z, h1z, l1z); split_bf16(v1.w, h1w, l1w);
            *(uint4*)&BsH[k2 * BW_STRIDE + bCol4] =
                make_uint4(pack_bf16x2(h0x, h1x), pack_bf16x2(h0y, h1y),
                           pack_bf16x2(h0z, h1z), pack_bf16x2(h0w, h1w));
            *(uint4*)&BsL[k2 * BW_STRIDE + bCol4] =
                make_uint4(pack_bf16x2(l0x, l1x), pack_bf16x2(l0y, l1y),
                           pack_bf16x2(l0z, l1z), pack_bf16x2(l0w, l1w));
        }
        __syncthreads();

        // ---- prefetch next tile (LDG in flight during compute) ----
        int k0n = k0 + 32;
        if (k0n < K) {
#pragma unroll
            for (int i = 0; i < 4; i++)
                aP[i] = *(const float4*)(A + (size_t)aRowG[i] * K + k0n + aCol4);
#pragma unroll
            for (int i = 0; i < 2; i++) {
                int k2 = bK2_0 + i * 8;
                const float* p0 = B + (size_t)(k0n + 2 * k2) * N + colBase + bCol4;
                bP0[i] = *(const float4*)p0;
                bP1[i] = *(const float4*)(p0 + N);
            }
        }

        // ---- compute: two k16 chunks per k0 ----
#pragma unroll
        for (int kk = 0; kk < 2; kk++) {
            const int kw = kk * 8;
            unsigned bh[4][2], bl[4][2];
#pragma unroll
            for (int nt = 0; nt < 4; nt++) {
                int c = warpN * 32 + nt * 8 + lq;
                bh[nt][0] = BsH[(kw + lr) * BW_STRIDE + c];
                bh[nt][1] = BsH[(kw + lr + 4) * BW_STRIDE + c];
                bl[nt][0] = BsL[(kw + lr) * BW_STRIDE + c];
                bl[nt][1] = BsL[(kw + lr + 4) * BW_STRIDE + c];
            }
#pragma unroll
            for (int mt = 0; mt < 4; mt++) {
                int r = warpM * 64 + mt * 16 + lq;
                int i0 = r * AW_STRIDE + kw + lr;
                int i1 = (r + 8) * AW_STRIDE + kw + lr;
                unsigned ah0 = AsH[i0], ah1 = AsH[i1], ah2 = AsH[i0 + 4], ah3 = AsH[i1 + 4];
                unsigned al0 = AsL[i0], al1 = AsL[i1], al2 = AsL[i0 + 4], al3 = AsL[i1 + 4];
#pragma unroll
                for (int nt = 0; nt < 4; nt++) {
                    MMA_BF16(acc[mt][nt], al0, al1, al2, al3, bh[nt][0], bh[nt][1]);
                    MMA_BF16(acc[mt][nt], ah0, ah1, ah2, ah3, bl[nt][0], bl[nt][1]);
                    MMA_BF16(acc[mt][nt], ah0, ah1, ah2, ah3, bh[nt][0], bh[nt][1]);
                }
            }
        }
        __syncthreads();
    }

#pragma unroll
    for (int mt = 0; mt < 4; mt++) {
        int r0 = rowBase + warpM * 64 + mt * 16 + lq;
#pragma unroll
        for (int nt = 0; nt < 4; nt++) {
            int c = colBase + warpN * 32 + nt * 8 + lr * 2;
            float b0 = bias ? bias[c] : 0.f;
            float b1 = bias ? bias[c + 1] : 0.f;
            if (r0 < M) {
                float v0 = acc[mt][nt][0] + b0;
                float v1 = acc[mt][nt][1] + b1;
                if (act) { v0 = fmaxf(v0, 0.f); v1 = fmaxf(v1, 0.f); }
                *(float2*)(C + (size_t)r0 * N + c) = make_float2(v0, v1);
            }
            if (r0 + 8 < M) {
                float v2 = acc[mt][nt][2] + b0;
                float v3 = acc[mt][nt][3] + b1;
                if (act) { v2 = fmaxf(v2, 0.f); v3 = fmaxf(v3, 0.f); }
                *(float2*)(C + (size_t)(r0 + 8) * N + c) = make_float2(v2, v3);
            }
        }
    }
}

// ---------------- per-node attention scalars ----------------
__global__ void k_es_ed(const float* __restrict__ a_src, const float* __restrict__ a_dst) {
    int n = blockIdx.x * (blockDim.x >> 5) + (threadIdx.x >> 5);
    int lane = threadIdx.x & 31;
    if (n >= NN) return;
    float4 hv = *(const float4*)(g_h + (size_t)n * DF + lane * 4);
    float4 as = *(const float4*)(a_src + lane * 4);
    float4 ad = *(const float4*)(a_dst + lane * 4);
    float s = hv.x * as.x + hv.y * as.y + hv.z * as.z + hv.w * as.w;
    float d = hv.x * ad.x + hv.y * ad.y + hv.z * ad.z + hv.w * ad.w;
#pragma unroll
    for (int o = 16; o > 0; o >>= 1) {
        s += __shfl_xor_sync(0xffffffff, s, o);
        d += __shfl_xor_sync(0xffffffff, d, o);
    }
    if (lane == 0) {
        g_es[n] = s;
        g_ed[n] = d;
    }
}

// ---------------- fused per-node softmax + aggregation (warp per node) ----------------
__global__ void k_node_aggr(const float* __restrict__ bias) {
    int n = blockIdx.x * (blockDim.x >> 5) + (threadIdx.x >> 5);
    int lane = threadIdx.x & 31;
    if (n >= NN) return;
    int r0 = g_rowstart[n];
    int r1 = g_rowstart[n + 1];
    float edn = g_ed[n];

    float m = -1e30f;
    for (int i = r0 + lane; i < r1; i += 32)
        m = fmaxf(m, leaky(g_es[g_csr[i]] + edn));
#pragma unroll
    for (int o = 16; o > 0; o >>= 1)
        m = fmaxf(m, __shfl_xor_sync(0xffffffff, m, o));

    float s = 0.f;
    for (int i = r0 + lane; i < r1; i += 32)
        s += expf(leaky(g_es[g_csr[i]] + edn) - m);
#pragma unroll
    for (int o = 16; o > 0; o >>= 1)
        s += __shfl_xor_sync(0xffffffff, s, o);
    float inv = 1.f / s;

    float4 acc = make_float4(0.f, 0.f, 0.f, 0.f);
    for (int i = r0; i < r1; i++) {
        int src = g_csr[i];
        float w = expf(leaky(g_es[src] + edn) - m) * inv;
        float4 hv = *(const float4*)(g_h + (size_t)src * DF + lane * 4);
        acc.x += w * hv.x;
        acc.y += w * hv.y;
        acc.z += w * hv.z;
        acc.w += w * hv.w;
    }
    float4 bv = *(const float4*)(bias + lane * 4);
    float4 r;
    r.x = leaky(acc.x + bv.x);
    r.y = leaky(acc.y + bv.y);
    r.z = leaky(acc.z + bv.z);
    r.w = leaky(acc.w + bv.w);
    *(float4*)(g_x + (size_t)n * DF + lane * 4) = r;
}

// ---------------- output head ----------------
__global__ void k_out(const float* __restrict__ Y, const float* __restrict__ Wout,
                      const float* __restrict__ bout, float* __restrict__ out) {
    int n = blockIdx.x * (blockDim.x >> 5) + (threadIdx.x >> 5);
    int lane = threadIdx.x & 31;
    if (n >= NN) return;
    float acc0 = 0.f, acc1 = 0.f, acc2 = 0.f, acc3 = 0.f;
    const float* y = Y + (size_t)n * DLIN;
    for (int k = lane; k < DLIN; k += 32) {
        float v = y[k];
        const float4 wv = *(const float4*)(Wout + k * 4);
        acc0 += v * wv.x;
        acc1 += v * wv.y;
        acc2 += v * wv.z;
        acc3 += v * wv.w;
    }
#pragma unroll
    for (int o = 16; o > 0; o >>= 1) {
        acc0 += __shfl_xor_sync(0xffffffff, acc0, o);
        acc1 += __shfl_xor_sync(0xffffffff, acc1, o);
        acc2 += __shfl_xor_sync(0xffffffff, acc2, o);
        acc3 += __shfl_xor_sync(0xffffffff, acc3, o);
    }
    if (lane == 0) {
        float4 r;
        r.x = acc0 + bout[0];
        r.y = acc1 + bout[1];
        r.z = acc2 + bout[2];
        r.w = acc3 + bout[3];
        *(float4*)(out + (size_t)n * 4) = r;
    }
}

extern "C" void kernel_launch(void* const* d_in, const int* in_sizes, int n_in,
                              void* d_out, int out_size) {
    const float *x, *conv_W, *conv_as, *conv_ad, *conv_b;
    const float *lin_W0, *lin_b0, *lin_W1, *lin_b1, *lin_W2, *lin_b2, *lin_Wout, *lin_bout;
    const void* ei;

    if (in_sizes[0] == NN * DF) {
        x        = (const float*)d_in[0];
        ei       = d_in[1];
        conv_W   = (const float*)d_in[2];
        conv_as  = (const float*)d_in[3];
        conv_ad  = (const float*)d_in[4];
        conv_b   = (const float*)d_in[5];
        lin_W0   = (const float*)d_in[6];
        lin_b0   = (const float*)d_in[7];
        lin_W1   = (const float*)d_in[8];
        lin_b1   = (const float*)d_in[9];
        lin_W2   = (const float*)d_in[10];
        lin_b2   = (const float*)d_in[11];
        lin_Wout = (const float*)d_in[12];
        lin_bout = (const float*)d_in[13];
    } else {
        conv_W   = (const float*)d_in[0];
        conv_ad  = (const float*)d_in[1];
        conv_as  = (const float*)d_in[2];
        conv_b   = (const float*)d_in[3];
        ei       = d_in[4];
        lin_W0   = (const float*)d_in[5];
        lin_W1   = (const float*)d_in[6];
        lin_W2   = (const float*)d_in[7];
        lin_Wout = (const float*)d_in[8];
        lin_b0   = (const float*)d_in[9];
        lin_b1   = (const float*)d_in[10];
        lin_b2   = (const float*)d_in[11];
        lin_bout = (const float*)d_in[12];
        x        = (const float*)d_in[13];
    }
    float* out = (float*)d_out;

    void *p_x, *p_h, *p_y0, *p_y1;
    cudaGetSymbolAddress(&p_x, g_x);
    cudaGetSymbolAddress(&p_h, g_h);
    cudaGetSymbolAddress(&p_y0, g_y0);
    cudaGetSymbolAddress(&p_y1, g_y1);

    // edges + CSR (once per launch)
    k_detect_dtype<<<1, 32>>>((const int*)ei);
    k_build_edges<<<(NEL + 255) / 256, 256>>>(ei);
    k_zero_deg<<<(NN + 255) / 256, 256>>>();
    k_hist<<<(NEL + 255) / 256, 256>>>();
    k_scan1<<<NBLK, 1024>>>();
    k_scan2<<<1, 32>>>();
    k_scan3<<<(NN + 255) / 256, 256>>>();
    k_scatter<<<(NEL + 255) / 256, 256>>>();

    dim3 grid128(1, (NN + 127) / 128);
    dim3 grid512(DLIN / 128, (NN + 127) / 128);
    const int wpb = 8;
    const int nodeBlocks = (NN + wpb - 1) / wpb;

    const float* curX = x;
    for (int layer = 0; layer < 3; layer++) {
        const float* W  = conv_W + (size_t)layer * DF * DF;
        const float* as = conv_as + (size_t)layer * DF;
        const float* ad = conv_ad + (size_t)layer * DF;
        const float* b  = conv_b + (size_t)layer * DF;

        k_mma<<<grid128, 256>>>(curX, W, nullptr, (float*)p_h, NN, DF, DF, 0);
        k_es_ed<<<nodeBlocks, wpb * 32>>>(as, ad);
        k_node_aggr<<<nodeBlocks, wpb * 32>>>(b);
        curX = (const float*)p_x;
    }

    k_mma<<<grid512, 256>>>((const float*)p_x, lin_W0, lin_b0, (float*)p_y0, NN, DLIN, DF, 1);
    k_mma<<<grid512, 256>>>((const float*)p_y0, lin_W1, lin_b1, (float*)p_y1, NN, DLIN, DLIN, 1);
    k_mma<<<grid512, 256>>>((const float*)p_y1, lin_W2, lin_b2, (float*)p_y0, NN, DLIN, DLIN, 1);
    k_out<<<nodeBlocks, wpb * 32>>>((const float*)p_y0, lin_Wout, lin_bout, out);
}